// round 6
// baseline (speedup 1.0000x reference)
#include <cuda_runtime.h>
#include <cuda_bf16.h>
#include <cstdint>

#define VOCAB   32000
#define EMB_DIM 2048
#define N_COMP  64
#define SEQ_L   128
#define BATCH   4096
#define SPLIT   8

// ---------------------------------------------------------------------------
// Static scratch (no allocation)
// ---------------------------------------------------------------------------
__device__ float         g_part[SPLIT][N_COMP * EMB_DIM];   // pool partials (4 MB)
__device__ __nv_bfloat16 g_BT_hi[EMB_DIM * N_COMP];         // pooled^T hi [n][k]
__device__ __nv_bfloat16 g_BT_lo[EMB_DIM * N_COMP];         // pooled^T lo [n][k]

// ---------------------------------------------------------------------------
// Kernel 1: pooled partial sums. grid=(N_COMP, 2, SPLIT), block=128.
// Each thread: 2 independent float4 columns (ILP-2), 16 tokens.
// ---------------------------------------------------------------------------
__global__ void pool_kernel(const int* __restrict__ ids,
                            const float* __restrict__ emb) {
    __shared__ int s_ids[SEQ_L / SPLIT];
    const int comp = blockIdx.x;
    const int z = blockIdx.z;
    const int t = threadIdx.x;
    const int TOK = SEQ_L / SPLIT;              // 16
    if (t < TOK) s_ids[t] = ids[comp * SEQ_L + z * TOK + t];
    __syncthreads();

    const int col0 = blockIdx.y * 256 + t;      // float4 col 0..511
    const int col1 = col0 + 128;
    const float4* __restrict__ emb4 = (const float4*)emb;

    float4 a0 = make_float4(0.f, 0.f, 0.f, 0.f);
    float4 a1 = make_float4(0.f, 0.f, 0.f, 0.f);
#pragma unroll
    for (int l = 0; l < TOK; l++) {
        const size_t rb = (size_t)s_ids[l] * (EMB_DIM / 4);
        float4 v0 = __ldcg(&emb4[rb + col0]);
        float4 v1 = __ldcg(&emb4[rb + col1]);
        a0.x += v0.x; a0.y += v0.y; a0.z += v0.z; a0.w += v0.w;
        a1.x += v1.x; a1.y += v1.y; a1.z += v1.z; a1.w += v1.w;
    }
    float4* dst = (float4*)g_part[z] + comp * (EMB_DIM / 4);
    dst[col0] = a0;
    dst[col1] = a1;
}

// ---------------------------------------------------------------------------
// bf16 split helpers
// ---------------------------------------------------------------------------
__device__ __forceinline__ void split_bf16(float v, __nv_bfloat16& hi, __nv_bfloat16& lo) {
    hi = __float2bfloat16_rn(v);
    lo = __float2bfloat16_rn(v - __bfloat162float(hi));
}
__device__ __forceinline__ uint32_t pack_bf2(__nv_bfloat16 a, __nv_bfloat16 b) {
    __nv_bfloat162 h = __halves2bfloat162(a, b);
    return *reinterpret_cast<uint32_t*>(&h);
}

// ---------------------------------------------------------------------------
// Kernel 2: pooled reduce + scale + bf16 split + transpose. grid=64, block=128.
// ---------------------------------------------------------------------------
__global__ void cvt_kernel() {
    const int lane = threadIdx.x & 31;
    const int ty = threadIdx.x >> 5;            // 0..3
    const int n = blockIdx.x * 32 + lane;       // 0..2047
    const int k0 = ty * 16;

    uint32_t h2[8], l2[8];
#pragma unroll
    for (int kp = 0; kp < 8; kp++) {
        __nv_bfloat16 ha, la, hb, lb;
        {
            const int k = k0 + 2 * kp;
            float s = 0.f;
#pragma unroll
            for (int z = 0; z < SPLIT; z++) s += g_part[z][k * EMB_DIM + n];
            split_bf16(s * (1.0f / SEQ_L), ha, la);
        }
        {
            const int k = k0 + 2 * kp + 1;
            float s = 0.f;
#pragma unroll
            for (int z = 0; z < SPLIT; z++) s += g_part[z][k * EMB_DIM + n];
            split_bf16(s * (1.0f / SEQ_L), hb, lb);
        }
        h2[kp] = pack_bf2(ha, hb);
        l2[kp] = pack_bf2(la, lb);
    }
    uint4* dh = (uint4*)g_BT_hi;   // row n = 8 uint4 (64 bf16)
    uint4* dl = (uint4*)g_BT_lo;
#pragma unroll
    for (int c = 0; c < 2; c++) {
        dh[n * 8 + ty * 2 + c] = make_uint4(h2[4*c], h2[4*c+1], h2[4*c+2], h2[4*c+3]);
        dl[n * 8 + ty * 2 + c] = make_uint4(l2[4*c], l2[4*c+1], l2[4*c+2], l2[4*c+3]);
    }
}

// ---------------------------------------------------------------------------
// Kernel 3: HMMA mix, persistent 2-half CTAs.
// CTA: 128 d-cols x 256 b-rows (two 128x128 halves, B smem reused).
// 256 threads (4 warps m x 2 warps n), ldmatrix fragment loads.
// ---------------------------------------------------------------------------
#define MMA16816(c, a, b0, b1) \
    asm volatile("mma.sync.aligned.m16n8k16.row.col.f32.bf16.bf16.f32 " \
        "{%0,%1,%2,%3}, {%4,%5,%6,%7}, {%8,%9}, {%0,%1,%2,%3};" \
        : "+f"((c)[0]), "+f"((c)[1]), "+f"((c)[2]), "+f"((c)[3]) \
        : "r"((a)[0]), "r"((a)[1]), "r"((a)[2]), "r"((a)[3]), "r"(b0), "r"(b1))

#define LDSM_X4(r0, r1, r2, r3, addr) \
    asm volatile("ldmatrix.sync.aligned.m8n8.x4.shared.b16 {%0,%1,%2,%3}, [%4];" \
        : "=r"(r0), "=r"(r1), "=r"(r2), "=r"(r3) : "r"(addr))

#define ROWB 144            // padded row pitch in bytes (72 bf16)
#define OFF_AH 0
#define OFF_AL (128 * ROWB)
#define OFF_BH (2 * 128 * ROWB)
#define OFF_BL (3 * 128 * ROWB)
#define MIX_SMEM (4 * 128 * ROWB)   // 73728 B

__device__ __forceinline__ uint32_t smem_u32(const void* p) {
    uint32_t a;
    asm("{ .reg .u64 t; cvta.to.shared.u64 t, %1; cvt.u32.u64 %0, t; }" : "=r"(a) : "l"(p));
    return a;
}

__global__ void __launch_bounds__(256)
mix_kernel(const float* __restrict__ ratio, float* __restrict__ out) {
    extern __shared__ char smem[];
    const uint32_t sb = smem_u32(smem);

    const int tid = threadIdx.x;
    const int wid = tid >> 5;
    const int lane = tid & 31;
    const int g = lane >> 2;          // 0..7
    const int t = lane & 3;           // 0..3
    const int dBase = blockIdx.x * 128;
    const int bSuper = blockIdx.y * 256;

    const int wm = wid & 3;           // m warp (0..3)
    const int wn = wid >> 2;          // n warp (0..1)

    // ldmatrix lane address components
    const int lr = lane & 7;
    const int seg = lane >> 3;                  // 0..3
    const int row_off = (seg & 1) * 8 + lr;
    const int k_off = (seg >> 1) * 8;

    const float4* __restrict__ rg = (const float4*)ratio;

    // --- A staging (fp32 -> bf16 hi/lo, 128 rows starting at rowBase) ---
    auto stage_A = [&](int rowBase) {
#pragma unroll
        for (int i = 0; i < 8; i++) {
            const int idx = i * 256 + tid;          // 0..2047
            const int b = idx >> 4;                 // row 0..127
            const int c = idx & 15;                 // float4 (4 cols)
            float4 v = __ldg(&rg[(size_t)(rowBase + b) * 16 + c]);
            __nv_bfloat16 h0, l0, h1, l1, h2, l2, h3, l3;
            split_bf16(v.x, h0, l0); split_bf16(v.y, h1, l1);
            split_bf16(v.z, h2, l2); split_bf16(v.w, h3, l3);
            const int off = b * ROWB + c * 8;
            *(uint2*)(smem + OFF_AH + off) = make_uint2(pack_bf2(h0, h1), pack_bf2(h2, h3));
            *(uint2*)(smem + OFF_AL + off) = make_uint2(pack_bf2(l0, l1), pack_bf2(l2, l3));
        }
    };

    // --- stage B once: rows dBase..+128, 8 int4 per row ---
    {
        const int4* __restrict__ bh = (const int4*)g_BT_hi;
        const int4* __restrict__ bl = (const int4*)g_BT_lo;
#pragma unroll
        for (int i = 0; i < 4; i++) {
            const int idx = i * 256 + tid;          // 0..1023
            const int r = idx >> 3, c = idx & 7;
            const int off = r * ROWB + c * 16;
            *(int4*)(smem + OFF_BH + off) = __ldg(&bh[(size_t)(dBase + r) * 8 + c]);
            *(int4*)(smem + OFF_BL + off) = __ldg(&bl[(size_t)(dBase + r) * 8 + c]);
        }
    }
    stage_A(bSuper);
    __syncthreads();

    float acc[2][8][4];

    // --- main: MMA over a staged A half ---
    auto do_mma = [&]() {
#pragma unroll
        for (int mt = 0; mt < 2; mt++)
#pragma unroll
            for (int nt = 0; nt < 8; nt++)
#pragma unroll
                for (int q = 0; q < 4; q++) acc[mt][nt][q] = 0.f;

#pragma unroll
        for (int ks = 0; ks < 4; ks++) {
            const int kb = (ks * 16 + k_off) * 2;   // byte offset along k

            uint32_t ah[2][4], al[2][4];
#pragma unroll
            for (int mt = 0; mt < 2; mt++) {
                const int m = wm * 32 + mt * 16 + row_off;
                LDSM_X4(ah[mt][0], ah[mt][1], ah[mt][2], ah[mt][3], sb + OFF_AH + m * ROWB + kb);
                LDSM_X4(al[mt][0], al[mt][1], al[mt][2], al[mt][3], sb + OFF_AL + m * ROWB + kb);
            }

#pragma unroll
            for (int p = 0; p < 4; p++) {           // covers nt = 2p, 2p+1
                const int n = wn * 64 + p * 16 + row_off;
                uint32_t bh0, bh1, bh2, bh3, bl0, bl1, bl2, bl3;
                LDSM_X4(bh0, bh1, bh2, bh3, sb + OFF_BH + n * ROWB + kb);
                LDSM_X4(bl0, bl1, bl2, bl3, sb + OFF_BL + n * ROWB + kb);
#pragma unroll
                for (int mt = 0; mt < 2; mt++) {
                    MMA16816(acc[mt][2*p],   ah[mt], bh0, bh2);
                    MMA16816(acc[mt][2*p],   ah[mt], bl0, bl2);
                    MMA16816(acc[mt][2*p],   al[mt], bh0, bh2);
                    MMA16816(acc[mt][2*p+1], ah[mt], bh1, bh3);
                    MMA16816(acc[mt][2*p+1], ah[mt], bl1, bl3);
                    MMA16816(acc[mt][2*p+1], al[mt], bh1, bh3);
                }
            }
        }
    };

    auto epilogue = [&](int rowBase) {
#pragma unroll
        for (int mt = 0; mt < 2; mt++) {
            const int m = rowBase + wm * 32 + mt * 16 + g;
#pragma unroll
            for (int nt = 0; nt < 8; nt++) {
                const int col = dBase + wn * 64 + nt * 8 + t * 2;
                *(float2*)&out[(size_t)m * EMB_DIM + col] =
                    make_float2(acc[mt][nt][0], acc[mt][nt][1]);
                *(float2*)&out[(size_t)(m + 8) * EMB_DIM + col] =
                    make_float2(acc[mt][nt][2], acc[mt][nt][3]);
            }
        }
    };

    // half 0
    do_mma();
    __syncthreads();            // everyone done reading A smem
    stage_A(bSuper + 128);      // overlap: A refill ...
    epilogue(bSuper);           // ... with half-0 stores
    __syncthreads();

    // half 1
    do_mma();
    epilogue(bSuper + 128);
}

// ---------------------------------------------------------------------------
// Launch
// ---------------------------------------------------------------------------
extern "C" void kernel_launch(void* const* d_in, const int* in_sizes, int n_in,
                              void* d_out, int out_size) {
    const int* ids = nullptr;
    const float* ratio = nullptr;
    const float* emb = nullptr;
    for (int i = 0; i < n_in; i++) {
        if (in_sizes[i] == N_COMP * SEQ_L)      ids   = (const int*)d_in[i];
        else if (in_sizes[i] == BATCH * N_COMP) ratio = (const float*)d_in[i];
        else                                     emb   = (const float*)d_in[i];
    }
    float* out = (float*)d_out;

    {   // pool partials
        dim3 grid(N_COMP, 2, SPLIT);            // 1024 blocks
        pool_kernel<<<grid, 128>>>(ids, emb);
    }
    {   // pooled reduce/split/transpose
        cvt_kernel<<<64, 128>>>();
    }
    {   // HMMA mix (persistent 2-half CTAs)
        static bool attr_set = false;
        if (!attr_set) {
            cudaFuncSetAttribute(mix_kernel,
                                 cudaFuncAttributeMaxDynamicSharedMemorySize,
                                 MIX_SMEM);
            attr_set = true;
        }
        dim3 grid(EMB_DIM / 128, BATCH / 256);  // (16, 16) = 256 CTAs
        mix_kernel<<<grid, 256, MIX_SMEM>>>(ratio, out);
    }
}

// round 7
// speedup vs baseline: 1.0352x; 1.0352x over previous
#include <cuda_runtime.h>
#include <cuda_bf16.h>
#include <cstdint>

#define VOCAB   32000
#define EMB_DIM 2048
#define N_COMP  64
#define SEQ_L   128
#define BATCH   4096
#define SPLIT   8
#define POOL_BLOCKS 2048          // 64 * 4 * 8
#define CVT_BLOCKS  64

// ---------------------------------------------------------------------------
// Static scratch (no allocation)
// ---------------------------------------------------------------------------
__device__ float         g_part[SPLIT][N_COMP * EMB_DIM];   // pool partials (4 MB)
__device__ __nv_bfloat16 g_BT_hi[EMB_DIM * N_COMP];         // pooled^T hi [n][k]
__device__ __nv_bfloat16 g_BT_lo[EMB_DIM * N_COMP];         // pooled^T lo [n][k]
__device__ unsigned int  g_counter;                         // monotonic ticket

// ---------------------------------------------------------------------------
// bf16 split helpers
// ---------------------------------------------------------------------------
__device__ __forceinline__ void split_bf16(float v, __nv_bfloat16& hi, __nv_bfloat16& lo) {
    hi = __float2bfloat16_rn(v);
    lo = __float2bfloat16_rn(v - __bfloat162float(hi));
}
__device__ __forceinline__ uint32_t pack_bf2(__nv_bfloat16 a, __nv_bfloat16 b) {
    __nv_bfloat162 h = __halves2bfloat162(a, b);
    return *reinterpret_cast<uint32_t*>(&h);
}

// ---------------------------------------------------------------------------
// Kernel 1: pooled partial sums (R5 config) + fused cvt tail.
// grid=(N_COMP, 4, SPLIT)=2048 blocks, block=128.
// Last 64 tickets perform the reduce+scale+split+transpose (cvt) work.
// Ticket targets are modular-monotonic -> replay-safe, no reset needed.
// ---------------------------------------------------------------------------
__global__ void pool_kernel(const int* __restrict__ ids,
                            const float* __restrict__ emb) {
    __shared__ int s_ids[SEQ_L / SPLIT];
    __shared__ unsigned int s_ticket;
    const int comp = blockIdx.x;
    const int z = blockIdx.z;
    const int t = threadIdx.x;
    const int TOK = SEQ_L / SPLIT;              // 16
    if (t < TOK) s_ids[t] = ids[comp * SEQ_L + z * TOK + t];
    __syncthreads();

    const int col4 = blockIdx.y * 128 + t;      // 0..511
    const float4* __restrict__ emb4 = (const float4*)emb;

    float4 acc = make_float4(0.f, 0.f, 0.f, 0.f);
#pragma unroll
    for (int l = 0; l < TOK; l++) {
        const int row = s_ids[l];
        float4 v = __ldg(&emb4[(size_t)row * (EMB_DIM / 4) + col4]);
        acc.x += v.x; acc.y += v.y; acc.z += v.z; acc.w += v.w;
    }
    ((float4*)g_part[z])[comp * (EMB_DIM / 4) + col4] = acc;

    // ---- ticket: last CVT_BLOCKS blocks run the cvt work ----
    __threadfence();
    __syncthreads();
    if (t == 0) s_ticket = atomicAdd(&g_counter, 1u);
    __syncthreads();
    const unsigned int ticket = s_ticket;
    const unsigned int phase = ticket & (POOL_BLOCKS - 1);
    if (phase < POOL_BLOCKS - CVT_BLOCKS) return;

    // wait for all pool partials of this replay
    const unsigned int target = ticket - phase + POOL_BLOCKS;
    if (t == 0) {
        while (atomicAdd(&g_counter, 0u) < target) { }
    }
    __syncthreads();
    __threadfence();

    // ---- cvt: reduce + scale + bf16 split + transpose (64 virtual blocks) ----
    const int vb = (int)(phase - (POOL_BLOCKS - CVT_BLOCKS));   // 0..63
    const int lane = t & 31;
    const int ty = t >> 5;                      // 0..3
    const int n = vb * 32 + lane;               // 0..2047
    const int k0 = ty * 16;

    uint32_t h2[8], l2[8];
#pragma unroll
    for (int kp = 0; kp < 8; kp++) {
        __nv_bfloat16 ha, la, hb, lb;
        {
            const int k = k0 + 2 * kp;
            float s = 0.f;
#pragma unroll
            for (int zz = 0; zz < SPLIT; zz++) s += g_part[zz][k * EMB_DIM + n];
            split_bf16(s * (1.0f / SEQ_L), ha, la);
        }
        {
            const int k = k0 + 2 * kp + 1;
            float s = 0.f;
#pragma unroll
            for (int zz = 0; zz < SPLIT; zz++) s += g_part[zz][k * EMB_DIM + n];
            split_bf16(s * (1.0f / SEQ_L), hb, lb);
        }
        h2[kp] = pack_bf2(ha, hb);
        l2[kp] = pack_bf2(la, lb);
    }
    uint4* dh = (uint4*)g_BT_hi;   // row n = 8 uint4 (64 bf16)
    uint4* dl = (uint4*)g_BT_lo;
#pragma unroll
    for (int c = 0; c < 2; c++) {
        dh[n * 8 + ty * 2 + c] = make_uint4(h2[4*c], h2[4*c+1], h2[4*c+2], h2[4*c+3]);
        dl[n * 8 + ty * 2 + c] = make_uint4(l2[4*c], l2[4*c+1], l2[4*c+2], l2[4*c+3]);
    }
}

// ---------------------------------------------------------------------------
// Kernel 2: HMMA mix with ldmatrix fragment loads (R5 version, unchanged).
// CTA: 128 b-rows x 128 d-cols, 256 threads (4 warps m x 2 warps n).
// ---------------------------------------------------------------------------
#define MMA16816(c, a, b0, b1) \
    asm volatile("mma.sync.aligned.m16n8k16.row.col.f32.bf16.bf16.f32 " \
        "{%0,%1,%2,%3}, {%4,%5,%6,%7}, {%8,%9}, {%0,%1,%2,%3};" \
        : "+f"((c)[0]), "+f"((c)[1]), "+f"((c)[2]), "+f"((c)[3]) \
        : "r"((a)[0]), "r"((a)[1]), "r"((a)[2]), "r"((a)[3]), "r"(b0), "r"(b1))

#define LDSM_X4(r0, r1, r2, r3, addr) \
    asm volatile("ldmatrix.sync.aligned.m8n8.x4.shared.b16 {%0,%1,%2,%3}, [%4];" \
        : "=r"(r0), "=r"(r1), "=r"(r2), "=r"(r3) : "r"(addr))

#define ROWB 144            // padded row pitch in bytes (72 bf16)
#define OFF_AH 0
#define OFF_AL (128 * ROWB)
#define OFF_BH (2 * 128 * ROWB)
#define OFF_BL (3 * 128 * ROWB)
#define MIX_SMEM (4 * 128 * ROWB)   // 73728 B

__device__ __forceinline__ uint32_t smem_u32(const void* p) {
    uint32_t a;
    asm("{ .reg .u64 t; cvta.to.shared.u64 t, %1; cvt.u32.u64 %0, t; }" : "=r"(a) : "l"(p));
    return a;
}

__global__ void __launch_bounds__(256)
mix_kernel(const float* __restrict__ ratio, float* __restrict__ out) {
    extern __shared__ char smem[];
    const uint32_t sb = smem_u32(smem);

    const int tid = threadIdx.x;
    const int wid = tid >> 5;
    const int lane = tid & 31;
    const int g = lane >> 2;          // 0..7
    const int t = lane & 3;           // 0..3
    const int dBase = blockIdx.x * 128;
    const int bBase = blockIdx.y * 128;

    // --- stage A: ratio[bBase..+128][0..64] fp32 -> bf16 hi/lo in smem ---
    {
        const float4* __restrict__ rg = (const float4*)ratio;
#pragma unroll
        for (int i = 0; i < 8; i++) {
            const int idx = i * 256 + tid;          // 0..2047
            const int b = idx >> 4;                 // row 0..127
            const int c = idx & 15;                 // float4 (4 cols)
            float4 v = __ldg(&rg[(size_t)(bBase + b) * 16 + c]);
            __nv_bfloat16 h0, l0, h1, l1, h2, l2, h3, l3;
            split_bf16(v.x, h0, l0); split_bf16(v.y, h1, l1);
            split_bf16(v.z, h2, l2); split_bf16(v.w, h3, l3);
            const int off = b * ROWB + c * 8;
            *(uint2*)(smem + OFF_AH + off) = make_uint2(pack_bf2(h0, h1), pack_bf2(h2, h3));
            *(uint2*)(smem + OFF_AL + off) = make_uint2(pack_bf2(l0, l1), pack_bf2(l2, l3));
        }
    }
    // --- stage B: g_BT rows dBase..+128, 8 int4 per row ---
    {
        const int4* __restrict__ bh = (const int4*)g_BT_hi;
        const int4* __restrict__ bl = (const int4*)g_BT_lo;
#pragma unroll
        for (int i = 0; i < 4; i++) {
            const int idx = i * 256 + tid;          // 0..1023
            const int r = idx >> 3, c = idx & 7;
            const int off = r * ROWB + c * 16;
            *(int4*)(smem + OFF_BH + off) = __ldg(&bh[(size_t)(dBase + r) * 8 + c]);
            *(int4*)(smem + OFF_BL + off) = __ldg(&bl[(size_t)(dBase + r) * 8 + c]);
        }
    }
    __syncthreads();

    const int wm = wid & 3;           // m warp (0..3)
    const int wn = wid >> 2;          // n warp (0..1)

    // ldmatrix lane address components
    const int lr = lane & 7;
    const int seg = lane >> 3;        // 0..3
    const int row_off = (seg & 1) * 8 + lr;
    const int k_off = (seg >> 1) * 8;

    float acc[2][8][4];
#pragma unroll
    for (int mt = 0; mt < 2; mt++)
#pragma unroll
        for (int nt = 0; nt < 8; nt++)
#pragma unroll
            for (int q = 0; q < 4; q++) acc[mt][nt][q] = 0.f;

#pragma unroll
    for (int ks = 0; ks < 4; ks++) {
        const int kb = (ks * 16 + k_off) * 2;       // byte offset along k

        uint32_t ah[2][4], al[2][4];
#pragma unroll
        for (int mt = 0; mt < 2; mt++) {
            const int m = wm * 32 + mt * 16 + row_off;
            LDSM_X4(ah[mt][0], ah[mt][1], ah[mt][2], ah[mt][3], sb + OFF_AH + m * ROWB + kb);
            LDSM_X4(al[mt][0], al[mt][1], al[mt][2], al[mt][3], sb + OFF_AL + m * ROWB + kb);
        }

#pragma unroll
        for (int p = 0; p < 4; p++) {               // covers nt = 2p, 2p+1
            const int n = wn * 64 + p * 16 + row_off;
            uint32_t bh0, bh1, bh2, bh3, bl0, bl1, bl2, bl3;
            LDSM_X4(bh0, bh1, bh2, bh3, sb + OFF_BH + n * ROWB + kb);
            LDSM_X4(bl0, bl1, bl2, bl3, sb + OFF_BL + n * ROWB + kb);
#pragma unroll
            for (int mt = 0; mt < 2; mt++) {
                MMA16816(acc[mt][2*p],   ah[mt], bh0, bh2);
                MMA16816(acc[mt][2*p],   ah[mt], bl0, bl2);
                MMA16816(acc[mt][2*p],   al[mt], bh0, bh2);
                MMA16816(acc[mt][2*p+1], ah[mt], bh1, bh3);
                MMA16816(acc[mt][2*p+1], ah[mt], bl1, bl3);
                MMA16816(acc[mt][2*p+1], al[mt], bh1, bh3);
            }
        }
    }

    // --- epilogue: direct float2 stores ---
#pragma unroll
    for (int mt = 0; mt < 2; mt++) {
        const int m = bBase + wm * 32 + mt * 16 + g;
#pragma unroll
        for (int nt = 0; nt < 8; nt++) {
            const int col = dBase + wn * 64 + nt * 8 + t * 2;
            *(float2*)&out[(size_t)m * EMB_DIM + col] =
                make_float2(acc[mt][nt][0], acc[mt][nt][1]);
            *(float2*)&out[(size_t)(m + 8) * EMB_DIM + col] =
                make_float2(acc[mt][nt][2], acc[mt][nt][3]);
        }
    }
}

// ---------------------------------------------------------------------------
// Launch
// ---------------------------------------------------------------------------
extern "C" void kernel_launch(void* const* d_in, const int* in_sizes, int n_in,
                              void* d_out, int out_size) {
    const int* ids = nullptr;
    const float* ratio = nullptr;
    const float* emb = nullptr;
    for (int i = 0; i < n_in; i++) {
        if (in_sizes[i] == N_COMP * SEQ_L)      ids   = (const int*)d_in[i];
        else if (in_sizes[i] == BATCH * N_COMP) ratio = (const float*)d_in[i];
        else                                     emb   = (const float*)d_in[i];
    }
    float* out = (float*)d_out;

    {   // pool partials + fused cvt tail
        dim3 grid(N_COMP, 4, SPLIT);            // 2048 blocks
        pool_kernel<<<grid, 128>>>(ids, emb);
    }
    {   // HMMA mix
        static bool attr_set = false;
        if (!attr_set) {
            cudaFuncSetAttribute(mix_kernel,
                                 cudaFuncAttributeMaxDynamicSharedMemorySize,
                                 MIX_SMEM);
            attr_set = true;
        }
        dim3 grid(EMB_DIM / 128, BATCH / 128);  // (16, 32)
        mix_kernel<<<grid, 256, MIX_SMEM>>>(ratio, out);
    }
}